// round 16
// baseline (speedup 1.0000x reference)
#include <cuda_runtime.h>
#include <cuda_bf16.h>
#include <cstdint>

// ---------------- problem constants ----------------
#define CN 100000      // nodes
#define CE 1600000     // edges
#define CH 128         // hidden
#define CIN 32         // input feat
#define CG 64          // graphs
#define NB_SCAN ((CN + 1023) / 1024)   // 98

// ---------------- static device scratch ----------------
__device__ float g_d13[(size_t)CN * 2];
__device__ float g_inv[CN];
__device__ int   g_deg[CN];
__device__ int   g_cur[CN];
__device__ int   g_rowptr[CN];
__device__ int   g_bsums[NB_SCAN + 8];
__device__ int   g_csr[CE];
__device__ float g_gs[CG * 3];
__device__ int   g_gcnt[CG];
__device__ int   g_sync[8];            // spin counters (c0,c1) + done ticket
// bf16 activation buffers
__device__ __nv_bfloat16 g_mh[(size_t)CN * CH];
__device__ __nv_bfloat16 g_h0h[(size_t)CN * CH];
__device__ __nv_bfloat16 g_h1h[(size_t)CN * CH];
__device__ __nv_bfloat16 g_xh[(size_t)CN * CIN];
// bf16 transposed weights [N=128][Ktot] K-major
__device__ __nv_bfloat16 g_w0h[128 * 64];
__device__ __nv_bfloat16 g_w1h[128 * 256];
__device__ __nv_bfloat16 g_w2h[128 * 256];
__device__ __nv_bfloat16 g_wah[128 * 128];

// ---------------- helpers ----------------
__device__ __forceinline__ void mma_bf16(float* d, const uint32_t* a, const uint32_t* b) {
    asm volatile(
        "mma.sync.aligned.m16n8k16.row.col.f32.bf16.bf16.f32 "
        "{%0,%1,%2,%3}, {%4,%5,%6,%7}, {%8,%9}, {%0,%1,%2,%3};"
        : "+f"(d[0]), "+f"(d[1]), "+f"(d[2]), "+f"(d[3])
        : "r"(a[0]), "r"(a[1]), "r"(a[2]), "r"(a[3]), "r"(b[0]), "r"(b[1]));
}
__device__ __forceinline__ void ldsm_x4(uint32_t* r, uint32_t addr) {
    asm volatile("ldmatrix.sync.aligned.m8n8.x4.shared.b16 {%0,%1,%2,%3}, [%4];"
        : "=r"(r[0]), "=r"(r[1]), "=r"(r[2]), "=r"(r[3]) : "r"(addr));
}
__device__ __forceinline__ uint32_t pack_bf(__nv_bfloat16 a, __nv_bfloat16 b) {
    __nv_bfloat162 t; t.x = a; t.y = b;
    return *(uint32_t*)&t;
}
__device__ __forceinline__ uint32_t smem_u32(const void* p) {
    uint32_t a;
    asm("{ .reg .u64 t; cvta.to.shared.u64 t, %1; cvt.u32.u64 %0, t; }" : "=r"(a) : "l"(p));
    return a;
}
__device__ __forceinline__ void cp8(uint32_t dst, const void* src, int bytes) {
    asm volatile("cp.async.ca.shared.global [%0], [%1], 8, %2;"
                 :: "r"(dst), "l"(src), "r"(bytes) : "memory");
}
#define CP_COMMIT() asm volatile("cp.async.commit_group;" ::: "memory")
#define CP_WAIT0()  asm volatile("cp.async.wait_group 0;" ::: "memory")
#define CP_WAIT1()  asm volatile("cp.async.wait_group 1;" ::: "memory")

__device__ __forceinline__ float quad_sum(float v) {
    v += __shfl_xor_sync(0xffffffffu, v, 1);
    v += __shfl_xor_sync(0xffffffffu, v, 2);
    return v;
}

// grid-wide barrier: all blocks resident by construction (98 blocks)
__device__ __forceinline__ void grid_sync(int* cnt, int nb) {
    __syncthreads();
    if (threadIdx.x == 0) {
        __threadfence();
        atomicAdd(cnt, 1);
        while (*(volatile int*)cnt < nb) { }
    }
    __syncthreads();
}

// ---------------- fused setup ----------------
__global__ void k_setup(const float* __restrict__ x,
                        const float* Wl0, const float* Wr0, const float* Wl1, const float* Wr1,
                        const float* Wl2, const float* Wr2, const float* Wa2,
                        __nv_bfloat16* xh,
                        __nv_bfloat16* w0h, __nv_bfloat16* w1h,
                        __nv_bfloat16* w2h, __nv_bfloat16* wah,
                        int* deg, float* gs, int* gcnt, int* syncc, int N) {
    int i = blockIdx.x * blockDim.x + threadIdx.x;
    if (i < N) deg[i] = 0;
    if (i < CG * 3) gs[i] = 0.f;
    if (i < CG) gcnt[i] = 0;
    if (i < 8) syncc[i] = 0;
    if (i < N * CIN) {
        xh[i] = __float2bfloat16_rn(x[i]);
    }
    float v;
    if (i < 8192) {
        int n = i >> 6, k = i & 63;
        v = (k < 32) ? Wl0[k * 128 + n] : Wr0[(k - 32) * 128 + n];
        w0h[i] = __float2bfloat16_rn(v);
    }
    int j = i - 8192;
    if (j >= 0 && j < 32768) {
        int n = j >> 8, k = j & 255;
        v = (k < 128) ? Wl1[k * 128 + n] : Wr1[(k - 128) * 128 + n];
        w1h[j] = __float2bfloat16_rn(v);
    }
    int lq = i - 40960;
    if (lq >= 0 && lq < 32768) {
        int n = lq >> 8, k = lq & 255;
        v = (k < 128) ? Wl2[k * 128 + n] : Wr2[(k - 128) * 128 + n];
        w2h[lq] = __float2bfloat16_rn(v);
    }
    int m = i - 73728;
    if (m >= 0 && m < 16384) {
        int n = m >> 7, k = m & 127;
        wah[m] = __float2bfloat16_rn(Wa2[k * 128 + n]);
    }
}

// ---------------- single-kernel CSR build (hist -> scan -> fill) ----------------
__global__ __launch_bounds__(1024)
void k_csr(const int* __restrict__ ei, int* deg, int* rowptr, int* cur,
           int* bsums, float* inv, int* csr, int* syncc, int N, int E) {
    __shared__ int sh[1024];
    int tid = threadIdx.x;
    int bid = blockIdx.x;
    int nb = gridDim.x;
    int gt = bid * 1024 + tid;
    int nth = nb * 1024;

    // ---- phase A: degree histogram ----
    for (int e = gt; e < E; e += nth)
        atomicAdd(&deg[ei[E + e]], 1);
    grid_sync(&syncc[0], nb);

    // ---- phase B: exclusive scan ----
    int i = gt;
    int v = (i < N) ? deg[i] : 0;
    sh[tid] = v;
    __syncthreads();
    for (int off = 1; off < 1024; off <<= 1) {
        int t = (tid >= off) ? sh[tid - off] : 0;
        __syncthreads();
        sh[tid] += t;
        __syncthreads();
    }
    if (tid == 1023) bsums[bid] = sh[1023];
    int local = sh[tid] - v;      // exclusive within block
    grid_sync(&syncc[1], nb);
    // block offset = sum of preceding block sums (nb <= 128, trivial)
    int boff = 0;
    for (int b = 0; b < bid; b++) boff += bsums[b];
    if (i < N) {
        int rp = boff + local;
        rowptr[i] = rp;
        cur[i] = rp;              // fill cursor starts at rowptr
        inv[i] = 1.0f / (float)(v > 0 ? v : 1);
    }
    grid_sync(&syncc[2], nb);

    // ---- phase C: fill (single atomic per edge) ----
    for (int e = gt; e < E; e += nth) {
        int s = ei[e];
        int d = ei[E + e];
        int pos = atomicAdd(&cur[d], 1);
        csr[pos] = s;
    }
}

// ---------------- aggregation (gather bf16, emit bf16 mean) ----------------
__global__ void k_agg128s(const __nv_bfloat16* __restrict__ hh,
                          const int* __restrict__ rowptr, const int* __restrict__ deg,
                          const float* __restrict__ inv, const int* __restrict__ csr,
                          __nv_bfloat16* __restrict__ mh, int N) {
    int w = (blockIdx.x * blockDim.x + threadIdx.x) >> 5;
    int lane = threadIdx.x & 31;
    if (w >= N) return;
    int start = rowptr[w];
    int d = deg[w];
    float a0 = 0.f, a1 = 0.f, a2 = 0.f, a3 = 0.f;
    int i = 0;
    for (; i + 4 <= d; i += 4) {
        int s0 = __ldg(&csr[start + i]);
        int s1 = __ldg(&csr[start + i + 1]);
        int s2 = __ldg(&csr[start + i + 2]);
        int s3 = __ldg(&csr[start + i + 3]);
        uint2 v0 = __ldg((const uint2*)(hh + (size_t)s0 * 128) + lane);
        uint2 v1 = __ldg((const uint2*)(hh + (size_t)s1 * 128) + lane);
        uint2 v2 = __ldg((const uint2*)(hh + (size_t)s2 * 128) + lane);
        uint2 v3 = __ldg((const uint2*)(hh + (size_t)s3 * 128) + lane);
#pragma unroll
        for (int q = 0; q < 4; q++) {
            uint2 v = (q == 0) ? v0 : (q == 1) ? v1 : (q == 2) ? v2 : v3;
            __nv_bfloat162 p01 = *(__nv_bfloat162*)&v.x;
            __nv_bfloat162 p23 = *(__nv_bfloat162*)&v.y;
            a0 += __bfloat162float(p01.x);
            a1 += __bfloat162float(p01.y);
            a2 += __bfloat162float(p23.x);
            a3 += __bfloat162float(p23.y);
        }
    }
    for (; i < d; i++) {
        int s = __ldg(&csr[start + i]);
        uint2 v = __ldg((const uint2*)(hh + (size_t)s * 128) + lane);
        __nv_bfloat162 p01 = *(__nv_bfloat162*)&v.x;
        __nv_bfloat162 p23 = *(__nv_bfloat162*)&v.y;
        a0 += __bfloat162float(p01.x);
        a1 += __bfloat162float(p01.y);
        a2 += __bfloat162float(p23.x);
        a3 += __bfloat162float(p23.y);
    }
    float iv = inv[w];
    ((uint2*)(mh + (size_t)w * 128))[lane] = make_uint2(
        pack_bf(__float2bfloat16_rn(a0 * iv), __float2bfloat16_rn(a1 * iv)),
        pack_bf(__float2bfloat16_rn(a2 * iv), __float2bfloat16_rn(a3 * iv)));
}

__global__ void k_agg32(const __nv_bfloat16* __restrict__ xh, const int* __restrict__ rowptr,
                        const int* __restrict__ deg, const float* __restrict__ inv,
                        const int* __restrict__ csr,
                        __nv_bfloat16* __restrict__ mh, int N) {
    int w = (blockIdx.x * blockDim.x + threadIdx.x) >> 5;
    int lane = threadIdx.x & 31;
    if (w >= N) return;
    int start = rowptr[w];
    int d = deg[w];
    float acc = 0.f;
    int i = 0;
    for (; i + 4 <= d; i += 4) {
        int s0 = __ldg(&csr[start + i]);
        int s1 = __ldg(&csr[start + i + 1]);
        int s2 = __ldg(&csr[start + i + 2]);
        int s3 = __ldg(&csr[start + i + 3]);
        float f0 = __bfloat162float(__ldg(&xh[(size_t)s0 * 32 + lane]));
        float f1 = __bfloat162float(__ldg(&xh[(size_t)s1 * 32 + lane]));
        float f2 = __bfloat162float(__ldg(&xh[(size_t)s2 * 32 + lane]));
        float f3 = __bfloat162float(__ldg(&xh[(size_t)s3 * 32 + lane]));
        acc += f0 + f1 + f2 + f3;
    }
    for (; i < d; i++) {
        int s = __ldg(&csr[start + i]);
        acc += __bfloat162float(__ldg(&xh[(size_t)s * 32 + lane]));
    }
    mh[(size_t)w * 32 + lane] = __float2bfloat16_rn(acc * inv[w]);
}

// ---------------- cp.async + ldmatrix pure-bf16 MMA GEMM ----------------
// mode 0: C = relu(A@W + bias) -> bf16 store Ch
// mode 1: + d13 head (no a1 store)
// mode 2: A generated in smem from d13; aux head + group atomics + fused final mean
#define APAD 20
#define TILE_BYTES 10240
#define BUFSZ      20480
#define WDB_OFF    40960
#define GEMM_SMEM  61440

__global__ __launch_bounds__(256, 2)
void k_gemm(const __nv_bfloat16* __restrict__ A1h,
            const __nv_bfloat16* __restrict__ A2h,
            const __nv_bfloat16* __restrict__ Wth,
            const float* __restrict__ bias,
            __nv_bfloat16* __restrict__ Ch,
            int mode, int M, int Kper,
            const float* __restrict__ Wfc, const float* __restrict__ bfc,
            const float* __restrict__ Wa1, const float* __restrict__ ba1,
            float* __restrict__ d13,
            const float* __restrict__ Wao, const float* __restrict__ bao,
            const int* __restrict__ batch, float* __restrict__ gs, int* __restrict__ gcnt,
            int* __restrict__ done, float* __restrict__ out) {
    extern __shared__ char dyn[];
    uint32_t sb = smem_u32(dyn);

    int tid = threadIdx.x;
    int lane = tid & 31;
    int w = tid >> 5;
    int wm = (w >> 2) * 64;
    int wn = (w & 3) * 32;
    int m0 = blockIdx.x * 128;
    int r = lane >> 2, cc = lane & 3;

    const bool genA = (mode == 2);
    const int nA = Kper >> 5;
    const int nch = (A2h != nullptr) ? 2 * nA : nA;
    const int Ktot = nch << 5;

    uint32_t offA[4], offB[2];
    {
        int arow = lane & 15;
        int akw  = (lane >> 4) * 4;
#pragma unroll
        for (int mt = 0; mt < 4; mt++)
            offA[mt] = (uint32_t)(((wm + mt * 16 + arow) * APAD + akw) * 4);
        int brow = (lane & 7) + ((lane & 16) >> 1);
        int bkw  = ((lane >> 3) & 1) * 4;
#pragma unroll
        for (int p = 0; p < 2; p++)
            offB[p] = (uint32_t)(((wn + p * 16 + brow) * APAD + bkw) * 4);
    }

    float acc[4][4][4];
#pragma unroll
    for (int a = 0; a < 4; a++)
#pragma unroll
        for (int b = 0; b < 4; b++)
#pragma unroll
            for (int q = 0; q < 4; q++) acc[a][b][q] = 0.f;

    auto issue = [&](int ch) {
        int buf = ch & 1;
        if (genA) {
            uint32_t bW = sb + WDB_OFF + buf * TILE_BYTES;
#pragma unroll
            for (int q = 0; q < 4; q++) {
                int lin = tid + (q << 8);
                int row = lin >> 3, g = lin & 7;
                uint32_t off = (uint32_t)(row * APAD + g * 2) * 4;
                cp8(bW + off, Wth + (size_t)row * Ktot + (ch << 5) + g * 4, 8);
            }
        } else {
            uint32_t bA = sb + buf * BUFSZ;
            const __nv_bfloat16* aH = (ch < nA) ? A1h : A2h;
            int coff = ((ch < nA) ? ch : ch - nA) << 5;
#pragma unroll
            for (int q = 0; q < 4; q++) {
                int lin = tid + (q << 8);
                int row = lin >> 3, g = lin & 7;
                int gm = m0 + row;
                int gmc = (gm < M) ? gm : (M - 1);
                int ok = (gm < M) ? 8 : 0;
                uint32_t off = (uint32_t)(row * APAD + g * 2) * 4;
                cp8(bA + off,              aH + (size_t)gmc * Kper + coff + g * 4, ok);
                cp8(bA + TILE_BYTES + off, Wth + (size_t)row * Ktot + (ch << 5) + g * 4, 8);
            }
        }
        CP_COMMIT();
    };

    issue(0);

    if (genA) {
#pragma unroll
        for (int q = 0; q < 16; q++) {
            int lin = tid + (q << 8);
            int row = lin >> 5;
            int g = lin & 31;
            int gm = m0 + row;
            float u0 = 0.f, u1 = 0.f, u2 = 0.f, u3 = 0.f;
            if (gm < M) {
                float d1 = d13[gm * 2 + 0];
                float d3 = d13[gm * 2 + 1];
                int col = g * 4;
                u0 = fmaxf(d1 * __ldg(&Wa1[col + 0]) + d3 * __ldg(&Wa1[128 + col + 0]) + __ldg(&ba1[col + 0]), 0.f);
                u1 = fmaxf(d1 * __ldg(&Wa1[col + 1]) + d3 * __ldg(&Wa1[128 + col + 1]) + __ldg(&ba1[col + 1]), 0.f);
                u2 = fmaxf(d1 * __ldg(&Wa1[col + 2]) + d3 * __ldg(&Wa1[128 + col + 2]) + __ldg(&ba1[col + 2]), 0.f);
                u3 = fmaxf(d1 * __ldg(&Wa1[col + 3]) + d3 * __ldg(&Wa1[128 + col + 3]) + __ldg(&ba1[col + 3]), 0.f);
            }
            int c = g >> 3;
            int word = (g & 7) * 2;
            *(uint2*)(dyn + c * TILE_BYTES + ((size_t)row * APAD + word) * 4) =
                make_uint2(pack_bf(__float2bfloat16_rn(u0), __float2bfloat16_rn(u1)),
                           pack_bf(__float2bfloat16_rn(u2), __float2bfloat16_rn(u3)));
        }
    }

    for (int ch = 0; ch < nch; ch++) {
        if (ch + 1 < nch) { issue(ch + 1); CP_WAIT1(); }
        else              { CP_WAIT0(); }
        __syncthreads();

        uint32_t Abase = genA ? (sb + ch * TILE_BYTES) : (sb + (ch & 1) * BUFSZ);
        uint32_t Wbase = genA ? (sb + WDB_OFF + (ch & 1) * TILE_BYTES)
                              : (sb + (ch & 1) * BUFSZ + TILE_BYTES);

#pragma unroll
        for (int ks = 0; ks < 2; ks++) {
            uint32_t kadd = ks * 32;
            uint32_t ah[4][4], bh[4][2];
#pragma unroll
            for (int mt = 0; mt < 4; mt++)
                ldsm_x4(ah[mt], Abase + offA[mt] + kadd);
#pragma unroll
            for (int p = 0; p < 2; p++)
                ldsm_x4(&bh[2 * p][0], Wbase + offB[p] + kadd);
#pragma unroll
            for (int mt = 0; mt < 4; mt++)
#pragma unroll
                for (int nt = 0; nt < 4; nt++)
                    mma_bf16(acc[mt][nt], ah[mt], bh[nt]);
        }
        __syncthreads();
    }

    // ---- epilogue ----
    float* sd = (float*)dyn;

    if (mode == 0) {
#pragma unroll
        for (int mt = 0; mt < 4; mt++) {
#pragma unroll
            for (int nt = 0; nt < 4; nt++) {
                int col = wn + nt * 8 + cc * 2;
                float b0 = __ldg(&bias[col]);
                float b1 = __ldg(&bias[col + 1]);
                int gm0 = m0 + wm + mt * 16 + r;
                int gm1 = gm0 + 8;
                float v0 = fmaxf(acc[mt][nt][0] + b0, 0.f);
                float v1 = fmaxf(acc[mt][nt][1] + b1, 0.f);
                float v2 = fmaxf(acc[mt][nt][2] + b0, 0.f);
                float v3 = fmaxf(acc[mt][nt][3] + b1, 0.f);
                if (gm0 < M)
                    *(uint32_t*)&Ch[(size_t)gm0 * 128 + col] =
                        pack_bf(__float2bfloat16_rn(v0), __float2bfloat16_rn(v1));
                if (gm1 < M)
                    *(uint32_t*)&Ch[(size_t)gm1 * 128 + col] =
                        pack_bf(__float2bfloat16_rn(v2), __float2bfloat16_rn(v3));
            }
        }
        return;
    }

    if (mode == 1) {
        if (tid < 256) sd[tid] = 0.f;
        __syncthreads();
#pragma unroll
        for (int mt = 0; mt < 4; mt++) {
            float s0a = 0.f, s2a = 0.f, s0b = 0.f, s2b = 0.f;
#pragma unroll
            for (int nt = 0; nt < 4; nt++) {
                int col = wn + nt * 8 + cc * 2;
                float b0 = __ldg(&bias[col]);
                float b1 = __ldg(&bias[col + 1]);
                float v0 = fmaxf(acc[mt][nt][0] + b0, 0.f);
                float v1 = fmaxf(acc[mt][nt][1] + b1, 0.f);
                float v2 = fmaxf(acc[mt][nt][2] + b0, 0.f);
                float v3 = fmaxf(acc[mt][nt][3] + b1, 0.f);
                float w00 = __ldg(&Wfc[col * 3 + 0]);
                float w01 = __ldg(&Wfc[col * 3 + 3]);
                float w20 = __ldg(&Wfc[col * 3 + 2]);
                float w21 = __ldg(&Wfc[col * 3 + 5]);
                s0a += v0 * w00 + v1 * w01;
                s2a += v0 * w20 + v1 * w21;
                s0b += v2 * w00 + v3 * w01;
                s2b += v2 * w20 + v3 * w21;
            }
            s0a = quad_sum(s0a); s2a = quad_sum(s2a);
            s0b = quad_sum(s0b); s2b = quad_sum(s2b);
            if (cc == 0) {
                int rr0 = wm + mt * 16 + r;
                atomicAdd(&sd[rr0 * 2 + 0], s0a);
                atomicAdd(&sd[rr0 * 2 + 1], s2a);
                atomicAdd(&sd[(rr0 + 8) * 2 + 0], s0b);
                atomicAdd(&sd[(rr0 + 8) * 2 + 1], s2b);
            }
        }
        __syncthreads();
        float bfc0 = __ldg(&bfc[0]);
        float bfc2 = __ldg(&bfc[2]);
        if ((w & 3) == 0 && cc == 0) {
#pragma unroll
            for (int mt = 0; mt < 4; mt++) {
                int rr0 = wm + mt * 16 + r;
                int gm0 = m0 + rr0, gm1 = gm0 + 8;
                if (gm0 < M) {
                    d13[gm0 * 2 + 0] = sd[rr0 * 2 + 0] + bfc0;
                    d13[gm0 * 2 + 1] = sd[rr0 * 2 + 1] + bfc2;
                }
                if (gm1 < M) {
                    d13[gm1 * 2 + 0] = sd[(rr0 + 8) * 2 + 0] + bfc0;
                    d13[gm1 * 2 + 1] = sd[(rr0 + 8) * 2 + 1] + bfc2;
                }
            }
        }
        return;
    }

    // mode == 2: aux head + group atomics + fused final
    if (tid < 128) sd[tid] = 0.f;
    __syncthreads();
#pragma unroll
    for (int mt = 0; mt < 4; mt++) {
        float pa = 0.f, pb = 0.f;
#pragma unroll
        for (int nt = 0; nt < 4; nt++) {
            int col = wn + nt * 8 + cc * 2;
            float b0 = __ldg(&bias[col]);
            float b1 = __ldg(&bias[col + 1]);
            float v0 = fmaxf(acc[mt][nt][0] + b0, 0.f);
            float v1 = fmaxf(acc[mt][nt][1] + b1, 0.f);
            float v2 = fmaxf(acc[mt][nt][2] + b0, 0.f);
            float v3 = fmaxf(acc[mt][nt][3] + b1, 0.f);
            float wo0 = __ldg(&Wao[col]);
            float wo1 = __ldg(&Wao[col + 1]);
            pa += v0 * wo0 + v1 * wo1;
            pb += v2 * wo0 + v3 * wo1;
        }
        pa = quad_sum(pa);
        pb = quad_sum(pb);
        if (cc == 0) {
            int rr0 = wm + mt * 16 + r;
            atomicAdd(&sd[rr0], pa);
            atomicAdd(&sd[rr0 + 8], pb);
        }
    }
    __syncthreads();
    if ((w & 3) == 0 && cc == 0) {
        float bao0 = __ldg(&bao[0]);
#pragma unroll
        for (int mt = 0; mt < 4; mt++) {
#pragma unroll
            for (int s = 0; s < 2; s++) {
                int rr = wm + mt * 16 + r + s * 8;
                int gm = m0 + rr;
                if (gm < M) {
                    float aux = sd[rr] + bao0;
                    int b = __ldg(&batch[gm]);
                    atomicAdd(&gs[b * 3 + 0], d13[gm * 2 + 0]);
                    atomicAdd(&gs[b * 3 + 1], aux);
                    atomicAdd(&gs[b * 3 + 2], d13[gm * 2 + 1]);
                    atomicAdd(&gcnt[b], 1);
                }
            }
        }
    }
    // last-block-done: final group mean
    __syncthreads();
    __shared__ int isLast;
    if (tid == 0) {
        __threadfence();
        int t = atomicAdd(done, 1);
        isLast = (t == (int)gridDim.x - 1) ? 1 : 0;
    }
    __syncthreads();
    if (isLast && tid < CG * 3) {
        int g = tid / 3;
        int c = *(volatile int*)&gcnt[g];
        float s = *(volatile float*)&gs[tid];
        out[tid] = s / (float)(c > 0 ? c : 1);
    }
}

// ---------------- host launch ----------------
extern "C" void kernel_launch(void* const* d_in, const int* in_sizes, int n_in,
                              void* d_out, int out_size) {
    const float* x     = (const float*)d_in[0];
    const int*   ei    = (const int*)d_in[1];
    const int*   batch = (const int*)d_in[2];
    const float* Wl0 = (const float*)d_in[3];
    const float* bl0 = (const float*)d_in[4];
    const float* Wr0 = (const float*)d_in[5];
    const float* Wl1 = (const float*)d_in[6];
    const float* bl1 = (const float*)d_in[7];
    const float* Wr1 = (const float*)d_in[8];
    const float* Wl2 = (const float*)d_in[9];
    const float* bl2 = (const float*)d_in[10];
    const float* Wr2 = (const float*)d_in[11];
    const float* Wfc = (const float*)d_in[12];
    const float* bfc = (const float*)d_in[13];
    const float* Wa1 = (const float*)d_in[14];
    const float* ba1 = (const float*)d_in[15];
    const float* Wa2 = (const float*)d_in[16];
    const float* ba2 = (const float*)d_in[17];
    const float* Wao = (const float*)d_in[18];
    const float* bao = (const float*)d_in[19];
    float* out = (float*)d_out;

    const int N = in_sizes[0] / CIN;
    const int E = in_sizes[1] / 2;

    float *d13, *inv, *gs;
    int *deg, *cur, *rowptr, *bsums, *csr, *gcnt, *syncc;
    __nv_bfloat16 *mh, *h0h, *h1h, *xh;
    __nv_bfloat16 *w0h, *w1h, *w2h, *wah;
    cudaGetSymbolAddress((void**)&d13,    g_d13);
    cudaGetSymbolAddress((void**)&inv,    g_inv);
    cudaGetSymbolAddress((void**)&deg,    g_deg);
    cudaGetSymbolAddress((void**)&cur,    g_cur);
    cudaGetSymbolAddress((void**)&rowptr, g_rowptr);
    cudaGetSymbolAddress((void**)&bsums,  g_bsums);
    cudaGetSymbolAddress((void**)&csr,    g_csr);
    cudaGetSymbolAddress((void**)&gs,     g_gs);
    cudaGetSymbolAddress((void**)&gcnt,   g_gcnt);
    cudaGetSymbolAddress((void**)&syncc,  g_sync);
    cudaGetSymbolAddress((void**)&mh,     g_mh);
    cudaGetSymbolAddress((void**)&h0h,    g_h0h);
    cudaGetSymbolAddress((void**)&h1h,    g_h1h);
    cudaGetSymbolAddress((void**)&xh,     g_xh);
    cudaGetSymbolAddress((void**)&w0h,    g_w0h);
    cudaGetSymbolAddress((void**)&w1h,    g_w1h);
    cudaGetSymbolAddress((void**)&w2h,    g_w2h);
    cudaGetSymbolAddress((void**)&wah,    g_wah);

    cudaFuncSetAttribute(k_gemm, cudaFuncAttributeMaxDynamicSharedMemorySize, GEMM_SMEM);

    const int gemmBlocks = (N + 127) / 128;
    const int warpNodeBlocks = (N * 32 + 255) / 256;

    // ---- fused setup + single-kernel CSR build ----
    k_setup<<<(N * CIN + 255) / 256, 256>>>(x, Wl0, Wr0, Wl1, Wr1, Wl2, Wr2, Wa2,
                                            xh, w0h, w1h, w2h, wah,
                                            deg, gs, gcnt, syncc, N);
    k_csr<<<NB_SCAN, 1024>>>(ei, deg, rowptr, cur, bsums, inv, csr, syncc, N, E);

    // ---- layer 0 (Kper=32, dual) -> h0 bf16 ----
    k_agg32<<<warpNodeBlocks, 256>>>(xh, rowptr, deg, inv, csr, mh, N);
    k_gemm<<<gemmBlocks, 256, GEMM_SMEM>>>(mh, xh, w0h, bl0,
                                           h0h, 0, N, CIN,
                                           nullptr, nullptr, nullptr, nullptr, nullptr,
                                           nullptr, nullptr, nullptr, nullptr, nullptr,
                                           nullptr, nullptr);

    // ---- layer 1 (Kper=128, dual) -> h1 bf16 ----
    k_agg128s<<<warpNodeBlocks, 256>>>(h0h, rowptr, deg, inv, csr, mh, N);
    k_gemm<<<gemmBlocks, 256, GEMM_SMEM>>>(mh, h0h, w1h, bl1,
                                           h1h, 0, N, CH,
                                           nullptr, nullptr, nullptr, nullptr, nullptr,
                                           nullptr, nullptr, nullptr, nullptr, nullptr,
                                           nullptr, nullptr);

    // ---- layer 2 (Kper=128, dual) + fused fc head -> d13 ----
    k_agg128s<<<warpNodeBlocks, 256>>>(h1h, rowptr, deg, inv, csr, mh, N);
    k_gemm<<<gemmBlocks, 256, GEMM_SMEM>>>(mh, h1h, w2h, bl2,
                                           nullptr, 1, N, CH,
                                           Wfc, bfc, nullptr, nullptr, d13,
                                           nullptr, nullptr, nullptr, nullptr, nullptr,
                                           nullptr, nullptr);

    // ---- aux GEMM (A from d13) + aux head + group accumulation + fused final ----
    k_gemm<<<gemmBlocks, 256, GEMM_SMEM>>>(nullptr, nullptr, wah, ba2,
                                           nullptr, 2, N, CH,
                                           nullptr, nullptr, Wa1, ba1, d13,
                                           Wao, bao, batch, gs, gcnt,
                                           &syncc[3], out);
}

// round 17
// speedup vs baseline: 1.0225x; 1.0225x over previous
#include <cuda_runtime.h>
#include <cuda_bf16.h>
#include <cstdint>

// ---------------- problem constants ----------------
#define CN 100000      // nodes
#define CE 1600000     // edges
#define CH 128         // hidden
#define CIN 32         // input feat
#define CG 64          // graphs
#define NB_SCAN ((CN + 1023) / 1024)   // 98

// ---------------- static device scratch ----------------
__device__ float g_d13[(size_t)CN * 2];
__device__ float g_inv[CN];
__device__ int   g_deg[CN];
__device__ int   g_cur[CN];
__device__ int   g_rowptr[CN];
__device__ int   g_bsums[NB_SCAN + 8];
__device__ int   g_csr[CE];
__device__ float g_gs[CG * 3];
__device__ int   g_gcnt[CG];
__device__ int   g_done[1];
// bf16 activation buffers
__device__ __nv_bfloat16 g_mh[(size_t)CN * CH];
__device__ __nv_bfloat16 g_h0h[(size_t)CN * CH];
__device__ __nv_bfloat16 g_h1h[(size_t)CN * CH];
__device__ __nv_bfloat16 g_xh[(size_t)CN * CIN];
// bf16 transposed weights [N=128][Ktot] K-major
__device__ __nv_bfloat16 g_w0h[128 * 64];
__device__ __nv_bfloat16 g_w1h[128 * 256];
__device__ __nv_bfloat16 g_w2h[128 * 256];
__device__ __nv_bfloat16 g_wah[128 * 128];

// ---------------- helpers ----------------
__device__ __forceinline__ void mma_bf16(float* d, const uint32_t* a, const uint32_t* b) {
    asm volatile(
        "mma.sync.aligned.m16n8k16.row.col.f32.bf16.bf16.f32 "
        "{%0,%1,%2,%3}, {%4,%5,%6,%7}, {%8,%9}, {%0,%1,%2,%3};"
        : "+f"(d[0]), "+f"(d[1]), "+f"(d[2]), "+f"(d[3])
        : "r"(a[0]), "r"(a[1]), "r"(a[2]), "r"(a[3]), "r"(b[0]), "r"(b[1]));
}
__device__ __forceinline__ void ldsm_x4(uint32_t* r, uint32_t addr) {
    asm volatile("ldmatrix.sync.aligned.m8n8.x4.shared.b16 {%0,%1,%2,%3}, [%4];"
        : "=r"(r[0]), "=r"(r[1]), "=r"(r[2]), "=r"(r[3]) : "r"(addr));
}
__device__ __forceinline__ uint32_t pack_bf(__nv_bfloat16 a, __nv_bfloat16 b) {
    __nv_bfloat162 t; t.x = a; t.y = b;
    return *(uint32_t*)&t;
}
__device__ __forceinline__ uint32_t smem_u32(const void* p) {
    uint32_t a;
    asm("{ .reg .u64 t; cvta.to.shared.u64 t, %1; cvt.u32.u64 %0, t; }" : "=r"(a) : "l"(p));
    return a;
}
__device__ __forceinline__ void cp8(uint32_t dst, const void* src, int bytes) {
    asm volatile("cp.async.ca.shared.global [%0], [%1], 8, %2;"
                 :: "r"(dst), "l"(src), "r"(bytes) : "memory");
}
#define CP_COMMIT() asm volatile("cp.async.commit_group;" ::: "memory")
#define CP_WAIT0()  asm volatile("cp.async.wait_group 0;" ::: "memory")
#define CP_WAIT1()  asm volatile("cp.async.wait_group 1;" ::: "memory")

__device__ __forceinline__ float quad_sum(float v) {
    v += __shfl_xor_sync(0xffffffffu, v, 1);
    v += __shfl_xor_sync(0xffffffffu, v, 2);
    return v;
}

// ---------------- fused setup + degree histogram ----------------
__global__ void k_setup(const float* __restrict__ x, const int* __restrict__ ei,
                        const float* Wl0, const float* Wr0, const float* Wl1, const float* Wr1,
                        const float* Wl2, const float* Wr2, const float* Wa2,
                        __nv_bfloat16* xh,
                        __nv_bfloat16* w0h, __nv_bfloat16* w1h,
                        __nv_bfloat16* w2h, __nv_bfloat16* wah,
                        int* deg, float* gs, int* gcnt, int* done, int N, int E) {
    int i = blockIdx.x * blockDim.x + threadIdx.x;
    if (i < N) deg[i] = 0;
    if (i < CG * 3) gs[i] = 0.f;
    if (i < CG) gcnt[i] = 0;
    if (i == 0) done[0] = 0;
    if (i < N * CIN) xh[i] = __float2bfloat16_rn(x[i]);
    float v;
    if (i < 8192) {
        int n = i >> 6, k = i & 63;
        v = (k < 32) ? Wl0[k * 128 + n] : Wr0[(k - 32) * 128 + n];
        w0h[i] = __float2bfloat16_rn(v);
    }
    int j = i - 8192;
    if (j >= 0 && j < 32768) {
        int n = j >> 8, k = j & 255;
        v = (k < 128) ? Wl1[k * 128 + n] : Wr1[(k - 128) * 128 + n];
        w1h[j] = __float2bfloat16_rn(v);
    }
    int lq = i - 40960;
    if (lq >= 0 && lq < 32768) {
        int n = lq >> 8, k = lq & 255;
        v = (k < 128) ? Wl2[k * 128 + n] : Wr2[(k - 128) * 128 + n];
        w2h[lq] = __float2bfloat16_rn(v);
    }
    int m = i - 73728;
    if (m >= 0 && m < 16384) {
        int n = m >> 7, k = m & 127;
        wah[m] = __float2bfloat16_rn(Wa2[k * 128 + n]);
    }
}

// degree histogram (separate: must run after deg is zeroed by k_setup's early blocks
// is not guaranteed within one kernel, so keep as its own small kernel)
__global__ void k_hist(const int* __restrict__ ei, int* deg, int E) {
    for (int e = blockIdx.x * blockDim.x + threadIdx.x; e < E; e += gridDim.x * blockDim.x)
        atomicAdd(&deg[ei[E + e]], 1);
}

__global__ void k_scan1(const int* __restrict__ deg, int* rowptr, int* bsums, int n) {
    __shared__ int sh[1024];
    int tid = threadIdx.x;
    int i = blockIdx.x * 1024 + tid;
    int v = (i < n) ? deg[i] : 0;
    sh[tid] = v;
    __syncthreads();
    for (int off = 1; off < 1024; off <<= 1) {
        int t = (tid >= off) ? sh[tid - off] : 0;
        __syncthreads();
        sh[tid] += t;
        __syncthreads();
    }
    if (i < n) rowptr[i] = sh[tid] - v;   // exclusive within block
    if (tid == 1023) bsums[blockIdx.x] = sh[1023];
}

// scan3: computes its own block prefix of bsums (nb <= 98), adds, seeds cur, inv
__global__ void k_scan3(int* rowptr, const int* __restrict__ bsums,
                        const int* __restrict__ deg, float* inv, int* cur, int n, int nb) {
    __shared__ int boff;
    if (threadIdx.x == 0) {
        int acc = 0;
        int b = blockIdx.x >> 2;           // scan3 blocks are 256 wide; 4 per scan1 block
        for (int q = 0; q < b; q++) acc += bsums[q];
        boff = acc;
    }
    __syncthreads();
    int i = blockIdx.x * blockDim.x + threadIdx.x;
    if (i < n) {
        int rp = rowptr[i] + boff;
        rowptr[i] = rp;
        cur[i] = rp;
        int d = deg[i];
        inv[i] = 1.0f / (float)(d > 0 ? d : 1);
    }
}

__global__ void k_fill(const int* __restrict__ ei, int* cur, int* csr, int E) {
    for (int e = blockIdx.x * blockDim.x + threadIdx.x; e < E; e += gridDim.x * blockDim.x) {
        int s = ei[e];
        int d = ei[E + e];
        int pos = atomicAdd(&cur[d], 1);
        csr[pos] = s;
    }
}

// ---------------- aggregation (gather bf16, emit bf16 mean) ----------------
__global__ void k_agg128s(const __nv_bfloat16* __restrict__ hh,
                          const int* __restrict__ rowptr, const int* __restrict__ deg,
                          const float* __restrict__ inv, const int* __restrict__ csr,
                          __nv_bfloat16* __restrict__ mh, int N) {
    int w = (blockIdx.x * blockDim.x + threadIdx.x) >> 5;
    int lane = threadIdx.x & 31;
    if (w >= N) return;
    int start = rowptr[w];
    int d = deg[w];
    float a0 = 0.f, a1 = 0.f, a2 = 0.f, a3 = 0.f;
    int i = 0;
    for (; i + 4 <= d; i += 4) {
        int s0 = __ldg(&csr[start + i]);
        int s1 = __ldg(&csr[start + i + 1]);
        int s2 = __ldg(&csr[start + i + 2]);
        int s3 = __ldg(&csr[start + i + 3]);
        uint2 v0 = __ldg((const uint2*)(hh + (size_t)s0 * 128) + lane);
        uint2 v1 = __ldg((const uint2*)(hh + (size_t)s1 * 128) + lane);
        uint2 v2 = __ldg((const uint2*)(hh + (size_t)s2 * 128) + lane);
        uint2 v3 = __ldg((const uint2*)(hh + (size_t)s3 * 128) + lane);
#pragma unroll
        for (int q = 0; q < 4; q++) {
            uint2 v = (q == 0) ? v0 : (q == 1) ? v1 : (q == 2) ? v2 : v3;
            __nv_bfloat162 p01 = *(__nv_bfloat162*)&v.x;
            __nv_bfloat162 p23 = *(__nv_bfloat162*)&v.y;
            a0 += __bfloat162float(p01.x);
            a1 += __bfloat162float(p01.y);
            a2 += __bfloat162float(p23.x);
            a3 += __bfloat162float(p23.y);
        }
    }
    for (; i < d; i++) {
        int s = __ldg(&csr[start + i]);
        uint2 v = __ldg((const uint2*)(hh + (size_t)s * 128) + lane);
        __nv_bfloat162 p01 = *(__nv_bfloat162*)&v.x;
        __nv_bfloat162 p23 = *(__nv_bfloat162*)&v.y;
        a0 += __bfloat162float(p01.x);
        a1 += __bfloat162float(p01.y);
        a2 += __bfloat162float(p23.x);
        a3 += __bfloat162float(p23.y);
    }
    float iv = inv[w];
    ((uint2*)(mh + (size_t)w * 128))[lane] = make_uint2(
        pack_bf(__float2bfloat16_rn(a0 * iv), __float2bfloat16_rn(a1 * iv)),
        pack_bf(__float2bfloat16_rn(a2 * iv), __float2bfloat16_rn(a3 * iv)));
}

__global__ void k_agg32(const __nv_bfloat16* __restrict__ xh, const int* __restrict__ rowptr,
                        const int* __restrict__ deg, const float* __restrict__ inv,
                        const int* __restrict__ csr,
                        __nv_bfloat16* __restrict__ mh, int N) {
    int w = (blockIdx.x * blockDim.x + threadIdx.x) >> 5;
    int lane = threadIdx.x & 31;
    if (w >= N) return;
    int start = rowptr[w];
    int d = deg[w];
    float acc = 0.f;
    int i = 0;
    for (; i + 4 <= d; i += 4) {
        int s0 = __ldg(&csr[start + i]);
        int s1 = __ldg(&csr[start + i + 1]);
        int s2 = __ldg(&csr[start + i + 2]);
        int s3 = __ldg(&csr[start + i + 3]);
        float f0 = __bfloat162float(__ldg(&xh[(size_t)s0 * 32 + lane]));
        float f1 = __bfloat162float(__ldg(&xh[(size_t)s1 * 32 + lane]));
        float f2 = __bfloat162float(__ldg(&xh[(size_t)s2 * 32 + lane]));
        float f3 = __bfloat162float(__ldg(&xh[(size_t)s3 * 32 + lane]));
        acc += f0 + f1 + f2 + f3;
    }
    for (; i < d; i++) {
        int s = __ldg(&csr[start + i]);
        acc += __bfloat162float(__ldg(&xh[(size_t)s * 32 + lane]));
    }
    mh[(size_t)w * 32 + lane] = __float2bfloat16_rn(acc * inv[w]);
}

// ---------------- cp.async + ldmatrix pure-bf16 MMA GEMM ----------------
// mode 0: C = relu(A@W + bias) -> bf16 store Ch
// mode 1: + d13 head (no a1 store)
// mode 2: A generated in smem from d13; aux head + group atomics + fused final
#define APAD 20
#define TILE_BYTES 10240
#define BUFSZ      20480
#define WDB_OFF    40960
#define GEMM_SMEM  61440

__global__ __launch_bounds__(256, 2)
void k_gemm(const __nv_bfloat16* __restrict__ A1h,
            const __nv_bfloat16* __restrict__ A2h,
            const __nv_bfloat16* __restrict__ Wth,
            const float* __restrict__ bias,
            __nv_bfloat16* __restrict__ Ch,
            int mode, int M, int Kper,
            const float* __restrict__ Wfc, const float* __restrict__ bfc,
            const float* __restrict__ Wa1, const float* __restrict__ ba1,
            float* __restrict__ d13,
            const float* __restrict__ Wao, const float* __restrict__ bao,
            const int* __restrict__ batch, float* __restrict__ gs, int* __restrict__ gcnt,
            int* __restrict__ done, float* __restrict__ out) {
    extern __shared__ char dyn[];
    uint32_t sb = smem_u32(dyn);

    int tid = threadIdx.x;
    int lane = tid & 31;
    int w = tid >> 5;
    int wm = (w >> 2) * 64;
    int wn = (w & 3) * 32;
    int m0 = blockIdx.x * 128;
    int r = lane >> 2, cc = lane & 3;

    const bool genA = (mode == 2);
    const int nA = Kper >> 5;
    const int nch = (A2h != nullptr) ? 2 * nA : nA;
    const int Ktot = nch << 5;

    uint32_t offA[4], offB[2];
    {
        int arow = lane & 15;
        int akw  = (lane >> 4) * 4;
#pragma unroll
        for (int mt = 0; mt < 4; mt++)
            offA[mt] = (uint32_t)(((wm + mt * 16 + arow) * APAD + akw) * 4);
        int brow = (lane & 7) + ((lane & 16) >> 1);
        int bkw  = ((lane >> 3) & 1) * 4;
#pragma unroll
        for (int p = 0; p < 2; p++)
            offB[p] = (uint32_t)(((wn + p * 16 + brow) * APAD + bkw) * 4);
    }

    float acc[4][4][4];
#pragma unroll
    for (int a = 0; a < 4; a++)
#pragma unroll
        for (int b = 0; b < 4; b++)
#pragma unroll
            for (int q = 0; q < 4; q++) acc[a][b][q] = 0.f;

    auto issue = [&](int ch) {
        int buf = ch & 1;
        if (genA) {
            uint32_t bW = sb + WDB_OFF + buf * TILE_BYTES;
#pragma unroll
            for (int q = 0; q < 4; q++) {
                int lin = tid + (q << 8);
                int row = lin >> 3, g = lin & 7;
                uint32_t off = (uint32_t)(row * APAD + g * 2) * 4;
                cp8(bW + off, Wth + (size_t)row * Ktot + (ch << 5) + g * 4, 8);
            }
        } else {
            uint32_t bA = sb + buf * BUFSZ;
            const __nv_bfloat16* aH = (ch < nA) ? A1h : A2h;
            int coff = ((ch < nA) ? ch : ch - nA) << 5;
#pragma unroll
            for (int q = 0; q < 4; q++) {
                int lin = tid + (q << 8);
                int row = lin >> 3, g = lin & 7;
                int gm = m0 + row;
                int gmc = (gm < M) ? gm : (M - 1);
                int ok = (gm < M) ? 8 : 0;
                uint32_t off = (uint32_t)(row * APAD + g * 2) * 4;
                cp8(bA + off,              aH + (size_t)gmc * Kper + coff + g * 4, ok);
                cp8(bA + TILE_BYTES + off, Wth + (size_t)row * Ktot + (ch << 5) + g * 4, 8);
            }
        }
        CP_COMMIT();
    };

    issue(0);

    if (genA) {
#pragma unroll
        for (int q = 0; q < 16; q++) {
            int lin = tid + (q << 8);
            int row = lin >> 5;
            int g = lin & 31;
            int gm = m0 + row;
            float u0 = 0.f, u1 = 0.f, u2 = 0.f, u3 = 0.f;
            if (gm < M) {
                float d1 = d13[gm * 2 + 0];
                float d3 = d13[gm * 2 + 1];
                int col = g * 4;
                u0 = fmaxf(d1 * __ldg(&Wa1[col + 0]) + d3 * __ldg(&Wa1[128 + col + 0]) + __ldg(&ba1[col + 0]), 0.f);
                u1 = fmaxf(d1 * __ldg(&Wa1[col + 1]) + d3 * __ldg(&Wa1[128 + col + 1]) + __ldg(&ba1[col + 1]), 0.f);
                u2 = fmaxf(d1 * __ldg(&Wa1[col + 2]) + d3 * __ldg(&Wa1[128 + col + 2]) + __ldg(&ba1[col + 2]), 0.f);
                u3 = fmaxf(d1 * __ldg(&Wa1[col + 3]) + d3 * __ldg(&Wa1[128 + col + 3]) + __ldg(&ba1[col + 3]), 0.f);
            }
            int c = g >> 3;
            int word = (g & 7) * 2;
            *(uint2*)(dyn + c * TILE_BYTES + ((size_t)row * APAD + word) * 4) =
                make_uint2(pack_bf(__float2bfloat16_rn(u0), __float2bfloat16_rn(u1)),
                           pack_bf(__float2bfloat16_rn(u2), __float2bfloat16_rn(u3)));
        }
    }

    for (int ch = 0; ch < nch; ch++) {
        if (ch + 1 < nch) { issue(ch + 1); CP_WAIT1(); }
        else              { CP_WAIT0(); }
        __syncthreads();

        uint32_t Abase = genA ? (sb + ch * TILE_BYTES) : (sb + (ch & 1) * BUFSZ);
        uint32_t Wbase = genA ? (sb + WDB_OFF + (ch & 1) * TILE_BYTES)
                              : (sb + (ch & 1) * BUFSZ + TILE_BYTES);

#pragma unroll
        for (int ks = 0; ks < 2; ks++) {
            uint32_t kadd = ks * 32;
            uint32_t ah[4][4], bh[4][2];
#pragma unroll
            for (int mt = 0; mt < 4; mt++)
                ldsm_x4(ah[mt], Abase + offA[mt] + kadd);
#pragma unroll
            for (int p = 0; p < 2; p++)
                ldsm_x4(&bh[2 * p][0], Wbase + offB[p] + kadd);
#pragma unroll
            for (int mt = 0; mt < 4; mt++)
#pragma unroll
                for (int nt = 0; nt < 4; nt++)
                    mma_bf16(acc[mt][nt], ah[mt], bh[nt]);
        }
        __syncthreads();
    }

    // ---- epilogue ----
    float* sd = (float*)dyn;

    if (mode == 0) {
#pragma unroll
        for (int mt = 0; mt < 4; mt++) {
#pragma unroll
            for (int nt = 0; nt < 4; nt++) {
                int col = wn + nt * 8 + cc * 2;
                float b0 = __ldg(&bias[col]);
                float b1 = __ldg(&bias[col + 1]);
                int gm0 = m0 + wm + mt * 16 + r;
                int gm1 = gm0 + 8;
                float v0 = fmaxf(acc[mt][nt][0] + b0, 0.f);
                float v1 = fmaxf(acc[mt][nt][1] + b1, 0.f);
                float v2 = fmaxf(acc[mt][nt][2] + b0, 0.f);
                float v3 = fmaxf(acc[mt][nt][3] + b1, 0.f);
                if (gm0 < M)
                    *(uint32_t*)&Ch[(size_t)gm0 * 128 + col] =
                        pack_bf(__float2bfloat16_rn(v0), __float2bfloat16_rn(v1));
                if (gm1 < M)
                    *(uint32_t*)&Ch[(size_t)gm1 * 128 + col] =
                        pack_bf(__float2bfloat16_rn(v2), __float2bfloat16_rn(v3));
            }
        }
        return;
    }

    if (mode == 1) {
        if (tid < 256) sd[tid] = 0.f;
        __syncthreads();
#pragma unroll
        for (int mt = 0; mt < 4; mt++) {
            float s0a = 0.f, s2a = 0.f, s0b = 0.f, s2b = 0.f;
#pragma unroll
            for (int nt = 0; nt < 4; nt++) {
                int col = wn + nt * 8 + cc * 2;
                float b0 = __ldg(&bias[col]);
                float b1 = __ldg(&bias[col + 1]);
                float v0 = fmaxf(acc[mt][nt][0] + b0, 0.f);
                float v1 = fmaxf(acc[mt][nt][1] + b1, 0.f);
                float v2 = fmaxf(acc[mt][nt][2] + b0, 0.f);
                float v3 = fmaxf(acc[mt][nt][3] + b1, 0.f);
                float w00 = __ldg(&Wfc[col * 3 + 0]);
                float w01 = __ldg(&Wfc[col * 3 + 3]);
                float w20 = __ldg(&Wfc[col * 3 + 2]);
                float w21 = __ldg(&Wfc[col * 3 + 5]);
                s0a += v0 * w00 + v1 * w01;
                s2a += v0 * w20 + v1 * w21;
                s0b += v2 * w00 + v3 * w01;
                s2b += v2 * w20 + v3 * w21;
            }
            s0a = quad_sum(s0a); s2a = quad_sum(s2a);
            s0b = quad_sum(s0b); s2b = quad_sum(s2b);
            if (cc == 0) {
                int rr0 = wm + mt * 16 + r;
                atomicAdd(&sd[rr0 * 2 + 0], s0a);
                atomicAdd(&sd[rr0 * 2 + 1], s2a);
                atomicAdd(&sd[(rr0 + 8) * 2 + 0], s0b);
                atomicAdd(&sd[(rr0 + 8) * 2 + 1], s2b);
            }
        }
        __syncthreads();
        float bfc0 = __ldg(&bfc[0]);
        float bfc2 = __ldg(&bfc[2]);
        if ((w & 3) == 0 && cc == 0) {
#pragma unroll
            for (int mt = 0; mt < 4; mt++) {
                int rr0 = wm + mt * 16 + r;
                int gm0 = m0 + rr0, gm1 = gm0 + 8;
                if (gm0 < M) {
                    d13[gm0 * 2 + 0] = sd[rr0 * 2 + 0] + bfc0;
                    d13[gm0 * 2 + 1] = sd[rr0 * 2 + 1] + bfc2;
                }
                if (gm1 < M) {
                    d13[gm1 * 2 + 0] = sd[(rr0 + 8) * 2 + 0] + bfc0;
                    d13[gm1 * 2 + 1] = sd[(rr0 + 8) * 2 + 1] + bfc2;
                }
            }
        }
        return;
    }

    // mode == 2: aux head + group atomics + fused final
    if (tid < 128) sd[tid] = 0.f;
    __syncthreads();
#pragma unroll
    for (int mt = 0; mt < 4; mt++) {
        float pa = 0.f, pb = 0.f;
#pragma unroll
        for (int nt = 0; nt < 4; nt++) {
            int col = wn + nt * 8 + cc * 2;
            float b0 = __ldg(&bias[col]);
            float b1 = __ldg(&bias[col + 1]);
            float v0 = fmaxf(acc[mt][nt][0] + b0, 0.f);
            float v1 = fmaxf(acc[mt][nt][1] + b1, 0.f);
            float v2 = fmaxf(acc[mt][nt][2] + b0, 0.f);
            float v3 = fmaxf(acc[mt][nt][3] + b1, 0.f);
            float wo0 = __ldg(&Wao[col]);
            float wo1 = __ldg(&Wao[col + 1]);
            pa += v0 * wo0 + v1 * wo1;
            pb += v2 * wo0 + v3 * wo1;
        }
        pa = quad_sum(pa);
        pb = quad_sum(pb);
        if (cc == 0) {
            int rr0 = wm + mt * 16 + r;
            atomicAdd(&sd[rr0], pa);
            atomicAdd(&sd[rr0 + 8], pb);
        }
    }
    __syncthreads();
    if ((w & 3) == 0 && cc == 0) {
        float bao0 = __ldg(&bao[0]);
#pragma unroll
        for (int mt = 0; mt < 4; mt++) {
#pragma unroll
            for (int s = 0; s < 2; s++) {
                int rr = wm + mt * 16 + r + s * 8;
                int gm = m0 + rr;
                if (gm < M) {
                    float aux = sd[rr] + bao0;
                    int b = __ldg(&batch[gm]);
                    atomicAdd(&gs[b * 3 + 0], d13[gm * 2 + 0]);
                    atomicAdd(&gs[b * 3 + 1], aux);
                    atomicAdd(&gs[b * 3 + 2], d13[gm * 2 + 1]);
                    atomicAdd(&gcnt[b], 1);
                }
            }
        }
    }
    __syncthreads();
    __shared__ int isLast;
    if (tid == 0) {
        __threadfence();
        int t = atomicAdd(done, 1);
        isLast = (t == (int)gridDim.x - 1) ? 1 : 0;
    }
    __syncthreads();
    if (isLast && tid < CG * 3) {
        int g = tid / 3;
        int c = *(volatile int*)&gcnt[g];
        float s = *(volatile float*)&gs[tid];
        out[tid] = s / (float)(c > 0 ? c : 1);
    }
}

// ---------------- host launch ----------------
extern "C" void kernel_launch(void* const* d_in, const int* in_sizes, int n_in,
                              void* d_out, int out_size) {
    const float* x     = (const float*)d_in[0];
    const int*   ei    = (const int*)d_in[1];
    const int*   batch = (const int*)d_in[2];
    const float* Wl0 = (const float*)d_in[3];
    const float* bl0 = (const float*)d_in[4];
    const float* Wr0 = (const float*)d_in[5];
    const float* Wl1 = (const float*)d_in[6];
    const float* bl1 = (const float*)d_in[7];
    const float* Wr1 = (const float*)d_in[8];
    const float* Wl2 = (const float*)d_in[9];
    const float* bl2 = (const float*)d_in[10];
    const float* Wr2 = (const float*)d_in[11];
    const float* Wfc = (const float*)d_in[12];
    const float* bfc = (const float*)d_in[13];
    const float* Wa1 = (const float*)d_in[14];
    const float* ba1 = (const float*)d_in[15];
    const float* Wa2 = (const float*)d_in[16];
    const float* ba2 = (const float*)d_in[17];
    const float* Wao = (const float*)d_in[18];
    const float* bao = (const float*)d_in[19];
    float* out = (float*)d_out;

    const int N = in_sizes[0] / CIN;
    const int E = in_sizes[1] / 2;

    float *d13, *inv, *gs;
    int *deg, *cur, *rowptr, *bsums, *csr, *gcnt, *done;
    __nv_bfloat16 *mh, *h0h, *h1h, *xh;
    __nv_bfloat16 *w0h, *w1h, *w2h, *wah;
    cudaGetSymbolAddress((void**)&d13,    g_d13);
    cudaGetSymbolAddress((void**)&inv,    g_inv);
    cudaGetSymbolAddress((void**)&deg,    g_deg);
    cudaGetSymbolAddress((void**)&cur,    g_cur);
    cudaGetSymbolAddress((void**)&rowptr, g_rowptr);
    cudaGetSymbolAddress((void**)&bsums,  g_bsums);
    cudaGetSymbolAddress((void**)&csr,    g_csr);
    cudaGetSymbolAddress((void**)&gs,     g_gs);
    cudaGetSymbolAddress((void**)&gcnt,   g_gcnt);
    cudaGetSymbolAddress((void**)&done,   g_done);
    cudaGetSymbolAddress((void**)&mh,     g_mh);
    cudaGetSymbolAddress((void**)&h0h,    g_h0h);
    cudaGetSymbolAddress((void**)&h1h,    g_h1h);
    cudaGetSymbolAddress((void**)&xh,     g_xh);
    cudaGetSymbolAddress((void**)&w0h,    g_w0h);
    cudaGetSymbolAddress((void**)&w1h,    g_w1h);
    cudaGetSymbolAddress((void**)&w2h,    g_w2h);
    cudaGetSymbolAddress((void**)&wah,    g_wah);

    cudaFuncSetAttribute(k_gemm, cudaFuncAttributeMaxDynamicSharedMemorySize, GEMM_SMEM);

    const int nbScan = (N + 1023) / 1024;
    const int gemmBlocks = (N + 127) / 128;
    const int warpNodeBlocks = (N * 32 + 255) / 256;

    // ---- setup + CSR build (scan2 folded into scan3; cur seeded in scan3) ----
    k_setup<<<(N * CIN + 255) / 256, 256>>>(x, ei, Wl0, Wr0, Wl1, Wr1, Wl2, Wr2, Wa2,
                                            xh, w0h, w1h, w2h, wah,
                                            deg, gs, gcnt, done, N, E);
    k_hist<<<4096, 256>>>(ei, deg, E);
    k_scan1<<<nbScan, 1024>>>(deg, rowptr, bsums, N);
    k_scan3<<<(N + 255) / 256, 256>>>(rowptr, bsums, deg, inv, cur, N, nbScan);
    k_fill<<<4096, 256>>>(ei, cur, csr, E);

    // ---- layer 0 (Kper=32, dual) -> h0 bf16 ----
    k_agg32<<<warpNodeBlocks, 256>>>(xh, rowptr, deg, inv, csr, mh, N);
    k_gemm<<<gemmBlocks, 256, GEMM_SMEM>>>(mh, xh, w0h, bl0,
                                           h0h, 0, N, CIN,
                                           nullptr, nullptr, nullptr, nullptr, nullptr,
                                           nullptr, nullptr, nullptr, nullptr, nullptr,
                                           nullptr, nullptr);

    // ---- layer 1 (Kper=128, dual) -> h1 bf16 ----
    k_agg128s<<<warpNodeBlocks, 256>>>(h0h, rowptr, deg, inv, csr, mh, N);
    k_gemm<<<gemmBlocks, 256, GEMM_SMEM>>>(mh, h0h, w1h, bl1,
                                           h1h, 0, N, CH,
                                           nullptr, nullptr, nullptr, nullptr, nullptr,
                                           nullptr, nullptr, nullptr, nullptr, nullptr,
                                           nullptr, nullptr);

    // ---- layer 2 (Kper=128, dual) + fused fc head -> d13 ----
    k_agg128s<<<warpNodeBlocks, 256>>>(h1h, rowptr, deg, inv, csr, mh, N);
    k_gemm<<<gemmBlocks, 256, GEMM_SMEM>>>(mh, h1h, w2h, bl2,
                                           nullptr, 1, N, CH,
                                           Wfc, bfc, nullptr, nullptr, d13,
                                           nullptr, nullptr, nullptr, nullptr, nullptr,
                                           nullptr, nullptr);

    // ---- aux GEMM (A from d13) + aux head + group accumulation + fused final ----
    k_gemm<<<gemmBlocks, 256, GEMM_SMEM>>>(nullptr, nullptr, wah, ba2,
                                           nullptr, 2, N, CH,
                                           nullptr, nullptr, Wa1, ba1, d13,
                                           Wao, bao, batch, gs, gcnt,
                                           done, out);
}